// round 3
// baseline (speedup 1.0000x reference)
#include <cuda_runtime.h>
#include <cstdint>

// Problem constants (fixed by the reference: N=64, T=2048, F=256)
#define CBS_N 64
#define CBS_T 2048
#define CBS_F 256
#define CBS_F4 (CBS_F / 4)   // 64 float4 per (n, t) row

// Findings so far:
//  - slices/lens are int32 (JAX x64 disabled) -> chunks output exact in R1.
//  - chunk_lens region is compared as float32 (harness __output__ dtype):
//    writing raw int32 bit patterns gave rel_err exactly 1.0 (denormals ~ 0).
//    Write float-encoded values instead.

__device__ __forceinline__ int imax_(int a, int b) { return a > b ? a : b; }
__device__ __forceinline__ int imin_(int a, int b) { return a < b ? a : b; }

// Main gather kernel: one float4 per thread.
// grid = (T*F4/256, N), block = 256
__global__ void chunk_by_slices_kernel(const float4* __restrict__ x,
                                       const int* __restrict__ slices,
                                       const int* __restrict__ lens,
                                       float4* __restrict__ out) {
    const int n = blockIdx.y;

    // Per-row parameters; uniform across the block -> L1 broadcast.
    const int s = slices[2 * n];
    const int e = slices[2 * n + 1];
    const int chunk_len = imax_(e - s, 0);
    const int left_pad  = (chunk_len == 0) ? 0 : imax_(-s, 0);
    const int start_    = imax_(s, 0);
    const int end_      = imin_(e, lens[n]);
    const int slice_len = imax_(end_ - start_, 0);

    const int tid = blockIdx.x * blockDim.x + threadIdx.x;  // over T*F4
    const int t = tid >> 6;          // / CBS_F4
    const int f = tid & (CBS_F4 - 1);

    const bool valid = (t >= left_pad) && (t < left_pad + slice_len);

    int src = start_ + t - left_pad;
    src = imin_(imax_(src, 0), CBS_T - 1);

    float4 v;
    if (valid) {
        v = x[(n * CBS_T + src) * CBS_F4 + f];
    } else {
        v = make_float4(0.f, 0.f, 0.f, 0.f);
    }
    out[(n * CBS_T + t) * CBS_F4 + f] = v;
}

// chunk_lens output, float-encoded (appended after the chunks tensor)
__global__ void chunk_lens_kernel(const int* __restrict__ slices,
                                  float* __restrict__ out_lens) {
    const int n = threadIdx.x;
    if (n < CBS_N) {
        const int s = slices[2 * n];
        const int e = slices[2 * n + 1];
        out_lens[n] = (float)imax_(e - s, 0);
    }
}

extern "C" void kernel_launch(void* const* d_in, const int* in_sizes, int n_in,
                              void* d_out, int out_size) {
    const float4* x      = (const float4*)d_in[0];
    const int*    slices = (const int*)d_in[1];
    const int*    lens   = (const int*)d_in[2];
    float4*       out    = (float4*)d_out;

    // 64 float4 per (n,t) row; 256 threads/block -> 4 rows per block.
    dim3 block(256);
    dim3 grid((CBS_T * CBS_F4) / 256, CBS_N);
    chunk_by_slices_kernel<<<grid, block>>>(x, slices, lens, out);

    // chunk_lens lives right after the chunks tensor.
    const long long chunks_elems = (long long)CBS_N * CBS_T * CBS_F;
    if ((long long)out_size >= chunks_elems + CBS_N) {
        chunk_lens_kernel<<<1, CBS_N>>>(slices, ((float*)d_out) + chunks_elems);
    }
}

// round 4
// speedup vs baseline: 1.1815x; 1.1815x over previous
#include <cuda_runtime.h>
#include <cstdint>

// Problem constants (fixed by the reference: N=64, T=2048, F=256)
#define CBS_N 64
#define CBS_T 2048
#define CBS_F 256
#define CBS_F4 (CBS_F / 4)   // 64 float4 per (n, t) row

// Findings:
//  - slices/lens are int32 (JAX x64 disabled).
//  - chunk_lens compared as float32 -> write float-encoded values.
//  - R3: separate chunk_lens kernel cost 3.9us of pure launch overhead
//    (12% of total). Fused here into blockIdx.x==0 of the main kernel.
//  - Main gather runs ~6.2 TB/s (near HBM streaming ceiling). Streaming
//    stores (__stcs) keep the never-re-read output out of L2.

__device__ __forceinline__ int imax_(int a, int b) { return a > b ? a : b; }
__device__ __forceinline__ int imin_(int a, int b) { return a < b ? a : b; }

// One float4 per thread. grid = (T*F4/256, N), block = 256.
__global__ void chunk_by_slices_fused_kernel(const float4* __restrict__ x,
                                             const int* __restrict__ slices,
                                             const int* __restrict__ lens,
                                             float4* __restrict__ out,
                                             float* __restrict__ out_lens) {
    const int n = blockIdx.y;

    // Per-row parameters; uniform across the block -> L1 broadcast.
    const int s = slices[2 * n];
    const int e = slices[2 * n + 1];
    const int chunk_len = imax_(e - s, 0);
    const int left_pad  = (chunk_len == 0) ? 0 : imax_(-s, 0);
    const int start_    = imax_(s, 0);
    const int end_      = imin_(e, lens[n]);
    const int slice_len = imax_(end_ - start_, 0);

    // Fused chunk_lens write: one thread per n.
    if (blockIdx.x == 0 && threadIdx.x == 0) {
        out_lens[n] = (float)chunk_len;
    }

    const int tid = blockIdx.x * blockDim.x + threadIdx.x;  // over T*F4
    const int t = tid >> 6;          // / CBS_F4
    const int f = tid & (CBS_F4 - 1);

    const bool valid = (t >= left_pad) && (t < left_pad + slice_len);

    int src = start_ + t - left_pad;
    src = imin_(imax_(src, 0), CBS_T - 1);

    float4 v;
    if (valid) {
        v = __ldg(&x[(n * CBS_T + src) * CBS_F4 + f]);
    } else {
        v = make_float4(0.f, 0.f, 0.f, 0.f);
    }
    // Output is never re-read: streaming store, evict-first in L2.
    __stcs(&out[(n * CBS_T + t) * CBS_F4 + f], v);
}

extern "C" void kernel_launch(void* const* d_in, const int* in_sizes, int n_in,
                              void* d_out, int out_size) {
    const float4* x      = (const float4*)d_in[0];
    const int*    slices = (const int*)d_in[1];
    const int*    lens   = (const int*)d_in[2];
    float4*       out    = (float4*)d_out;

    const long long chunks_elems = (long long)CBS_N * CBS_T * CBS_F;
    float* out_lens = ((float*)d_out) + chunks_elems;

    // 64 float4 per (n,t) row; 256 threads/block -> 4 rows per block.
    dim3 block(256);
    dim3 grid((CBS_T * CBS_F4) / 256, CBS_N);
    chunk_by_slices_fused_kernel<<<grid, block>>>(x, slices, lens, out, out_lens);
}